// round 1
// baseline (speedup 1.0000x reference)
#include <cuda_runtime.h>
#include <math.h>

// Problem constants (fixed by the dataset)
#define BB      32768      // batch
#define HH      128        // hidden
#define GG      512        // 4*H gates
#define EE      16         // embedding dim
#define NOBS    9          // observed frames
#define NOUT    19         // 8 obs outputs + 11 pred outputs

// Tiling
#define MROWS   64         // batch rows per CTA
#define NTHR    512        // threads per CTA
#define KC      16         // k-chunk for W_hh staging

// Persistent state / preprocessed weights (device globals: allocation-free)
__device__ float g_h[BB * HH];
__device__ float g_c[BB * HH];
__device__ float g_Wt[HH * GG];    // W_hh transposed: [k][j]
__device__ float g_Wti[EE * GG];   // W_ih transposed: [k][j]
__device__ float g_bias[GG];       // b_ih + b_hh

__device__ __forceinline__ float sigf(float x) {
    return 1.0f / (1.0f + expf(-x));
}

// ---------------------------------------------------------------------------
// Prep: zero h/c, transpose weights, fuse biases. Runs every launch
// (deterministic; cheap: ~8.6M stores, one wave).
// ---------------------------------------------------------------------------
__global__ void prep_kernel(const float* __restrict__ W_ih,
                            const float* __restrict__ b_ih,
                            const float* __restrict__ W_hh,
                            const float* __restrict__ b_hh) {
    int idx = blockIdx.x * blockDim.x + threadIdx.x;
    int stride = gridDim.x * blockDim.x;
    for (int i = idx; i < BB * HH; i += stride) {
        g_h[i] = 0.0f;
        g_c[i] = 0.0f;
    }
    for (int i = idx; i < HH * GG; i += stride) {
        int k = i / GG, j = i - k * GG;
        g_Wt[i] = W_hh[j * HH + k];
    }
    for (int i = idx; i < EE * GG; i += stride) {
        int k = i / GG, j = i - k * GG;
        g_Wti[i] = W_ih[j * EE + k];
    }
    for (int i = idx; i < GG; i += stride) {
        g_bias[i] = b_ih[i] + b_hh[i];
    }
}

// ---------------------------------------------------------------------------
// One LSTM time step (fused embed + gates GEMM + cell + readout).
//   delta = dA - dB  (B x 2), base = dA, writes out_pos (B x 2)
// Thread (rg, j): j = gate column 0..127, rg = row-group 0..3 (16 rows each).
// Thread accumulates the full (i,f,g,o) quad for its 16 rows -> cell update
// is thread-local.
// ---------------------------------------------------------------------------
__global__ void __launch_bounds__(NTHR, 1)
lstm_step(const float* __restrict__ dA,
          const float* __restrict__ dB,
          float* __restrict__ out_pos,
          const float* __restrict__ W_emb,
          const float* __restrict__ b_emb,
          const float* __restrict__ W_out,
          const float* __restrict__ b_out) {
    extern __shared__ float smem[];
    float* h_s = smem;                     // MROWS*HH   = 8192 f
    float* e_s = h_s + MROWS * HH;         // MROWS*EE   = 1024 f
    float* w_s = e_s + MROWS * EE;         // KC*GG      = 8192 f (reused)

    const int tid  = threadIdx.x;
    const int j    = tid & 127;
    const int rg   = tid >> 7;             // 0..3
    const int row0 = blockIdx.x * MROWS;

    // --- stage h tile (coalesced float4) ---
    {
        const float4* src = (const float4*)(g_h + (size_t)row0 * HH);
        float4* dst = (float4*)h_s;
        #pragma unroll
        for (int i = tid; i < MROWS * HH / 4; i += NTHR) dst[i] = src[i];
    }
    // --- embeddings: e = relu(W_emb @ delta + b_emb) ---
    for (int i = tid; i < MROWS * EE; i += NTHR) {
        int r = i >> 4, ei = i & 15;
        int grow = row0 + r;
        float dx = dA[grow * 2 + 0] - dB[grow * 2 + 0];
        float dy = dA[grow * 2 + 1] - dB[grow * 2 + 1];
        float v = fmaf(W_emb[ei * 2 + 0], dx,
                  fmaf(W_emb[ei * 2 + 1], dy, b_emb[ei]));
        e_s[r * EE + ei] = fmaxf(v, 0.0f);
    }
    __syncthreads();

    float acc[16][4];
    #pragma unroll
    for (int r = 0; r < 16; r++)
        #pragma unroll
        for (int q = 0; q < 4; q++) acc[r][q] = 0.0f;

    // --- main GEMM: gates += h @ W_hh^T, staged KC rows of Wt at a time ---
    for (int kc = 0; kc < HH; kc += KC) {
        {
            const float4* src = (const float4*)(g_Wt + kc * GG);
            float4* dst = (float4*)w_s;
            #pragma unroll
            for (int i = tid; i < KC * GG / 4; i += NTHR) dst[i] = src[i];
        }
        __syncthreads();
        #pragma unroll
        for (int k = 0; k < KC; k++) {
            float w0 = w_s[k * GG + j];
            float w1 = w_s[k * GG + 128 + j];
            float w2 = w_s[k * GG + 256 + j];
            float w3 = w_s[k * GG + 384 + j];
            #pragma unroll
            for (int r = 0; r < 16; r++) {
                float hv = h_s[(rg * 16 + r) * HH + kc + k];   // warp broadcast
                acc[r][0] = fmaf(hv, w0, acc[r][0]);
                acc[r][1] = fmaf(hv, w1, acc[r][1]);
                acc[r][2] = fmaf(hv, w2, acc[r][2]);
                acc[r][3] = fmaf(hv, w3, acc[r][3]);
            }
        }
        __syncthreads();
    }

    // --- input GEMM: gates += e @ W_ih^T (K = 16) ---
    {
        const float4* src = (const float4*)g_Wti;
        float4* dst = (float4*)w_s;
        #pragma unroll
        for (int i = tid; i < EE * GG / 4; i += NTHR) dst[i] = src[i];
    }
    __syncthreads();
    #pragma unroll
    for (int k = 0; k < EE; k++) {
        float w0 = w_s[k * GG + j];
        float w1 = w_s[k * GG + 128 + j];
        float w2 = w_s[k * GG + 256 + j];
        float w3 = w_s[k * GG + 384 + j];
        #pragma unroll
        for (int r = 0; r < 16; r++) {
            float ev = e_s[(rg * 16 + r) * EE + k];
            acc[r][0] = fmaf(ev, w0, acc[r][0]);
            acc[r][1] = fmaf(ev, w1, acc[r][1]);
            acc[r][2] = fmaf(ev, w2, acc[r][2]);
            acc[r][3] = fmaf(ev, w3, acc[r][3]);
        }
    }
    __syncthreads();   // about to overwrite h_s with h2

    // --- LSTM cell (thread-local) ---
    const float bi = g_bias[j];
    const float bf = g_bias[128 + j];
    const float bg = g_bias[256 + j];
    const float bo = g_bias[384 + j];
    #pragma unroll
    for (int r = 0; r < 16; r++) {
        int lr = rg * 16 + r;
        size_t gidx = (size_t)(row0 + lr) * HH + j;
        float iv = sigf(acc[r][0] + bi);
        float fv = sigf(acc[r][1] + bf);
        float gv = tanhf(acc[r][2] + bg);
        float ov = sigf(acc[r][3] + bo);
        float c2 = fmaf(fv, g_c[gidx], iv * gv);
        float h2 = ov * tanhf(c2);
        g_c[gidx] = c2;
        g_h[gidx] = h2;
        h_s[lr * HH + j] = h2;
    }
    __syncthreads();

    // --- readout: pos = base + (h2 @ W_out[0:2]^T + b_out[0:2]) ---
    // warp w handles rows [4w, 4w+4)
    const int warp = tid >> 5;
    const int lane = tid & 31;
    const float bo0 = b_out[0], bo1 = b_out[1];
    #pragma unroll
    for (int rr = 0; rr < 4; rr++) {
        int lr = warp * 4 + rr;
        int grow = row0 + lr;
        float s0 = 0.0f, s1 = 0.0f;
        #pragma unroll
        for (int k = lane; k < HH; k += 32) {
            float hv = h_s[lr * HH + k];
            s0 = fmaf(hv, W_out[0 * HH + k], s0);
            s1 = fmaf(hv, W_out[1 * HH + k], s1);
        }
        #pragma unroll
        for (int off = 16; off; off >>= 1) {
            s0 += __shfl_xor_sync(0xFFFFFFFFu, s0, off);
            s1 += __shfl_xor_sync(0xFFFFFFFFu, s1, off);
        }
        if (lane == 0) {
            out_pos[grow * 2 + 0] = dA[grow * 2 + 0] + s0 + bo0;   // base == dA
            out_pos[grow * 2 + 1] = dA[grow * 2 + 1] + s1 + bo1;
        }
    }
}

// ---------------------------------------------------------------------------
extern "C" void kernel_launch(void* const* d_in, const int* in_sizes, int n_in,
                              void* d_out, int out_size) {
    const float* observed = (const float*)d_in[0];   // (9, B, 2)
    const float* W_emb    = (const float*)d_in[1];   // (16, 2)
    const float* b_emb    = (const float*)d_in[2];   // (16,)
    const float* W_ih     = (const float*)d_in[3];   // (512, 16)
    const float* b_ih     = (const float*)d_in[4];   // (512,)
    const float* W_hh     = (const float*)d_in[5];   // (512, 128)
    const float* b_hh     = (const float*)d_in[6];   // (512,)
    const float* W_out    = (const float*)d_in[7];   // (5, 128)
    const float* b_out    = (const float*)d_in[8];   // (5,)
    float* out = (float*)d_out;                      // (19, B, 2)

    static bool attr_set = false;
    const int smem_bytes = (MROWS * HH + MROWS * EE + KC * GG) * (int)sizeof(float);
    if (!attr_set) {
        cudaFuncSetAttribute(lstm_step,
                             cudaFuncAttributeMaxDynamicSharedMemorySize,
                             smem_bytes);
        attr_set = true;
    }

    prep_kernel<<<2048, 256>>>(W_ih, b_ih, W_hh, b_hh);

    const int grid = BB / MROWS;   // 512 CTAs
    const size_t rowstride = (size_t)BB * 2;

    // observation phase: t = 1..8 writes output row t-1
    for (int t = 1; t < NOBS; t++) {
        lstm_step<<<grid, NTHR, smem_bytes>>>(
            observed + (size_t)t * rowstride,
            observed + (size_t)(t - 1) * rowstride,
            out + (size_t)(t - 1) * rowstride,
            W_emb, b_emb, W_out, b_out);
    }
    // prediction phase: output rows 8..18; delta = out[r-1]-out[r-2], base = out[r-1]
    for (int r = NOBS - 1; r < NOUT; r++) {
        lstm_step<<<grid, NTHR, smem_bytes>>>(
            out + (size_t)(r - 1) * rowstride,
            out + (size_t)(r - 2) * rowstride,
            out + (size_t)r * rowstride,
            W_emb, b_emb, W_out, b_out);
    }
}

// round 4
// speedup vs baseline: 2.8925x; 2.8925x over previous
#include <cuda_runtime.h>
#include <cuda_bf16.h>
#include <math.h>
#include <stdint.h>

// Arch guard: the harness also emits a compute_103 (non-'a') PTX pass where
// tcgen05 is illegal. Real body only in the arch-specific pass.
#if !defined(__CUDA_ARCH__) || defined(__CUDA_ARCH_FEAT_SM103_ALL)
#define HAS_TCGEN05 1
#else
#define HAS_TCGEN05 0
#endif

// ---------------- problem constants ----------------
#define BB   32768
#define HH   128
#define EE   16
#define KK   144          // combined K = H (128) + E (16)
#define NOBS 9
#define NOUT 19

#define MT     128        // M rows per CTA
#define NT     64         // N per ntile
#define NTILES 8          // 8*64 = 512 gate columns
#define NCTA   (BB/MT)    // 256
#define NTHR   256

// ---------------- smem layout (bytes) ----------------
#define SM_TMEM   0
#define SM_MBAR   8
#define SM_BIASQ  16                  // 512 f
#define SM_WOUT   2064                // 256 f (rows 0,1 of W_out)
#define SM_PART   3088                // 2*128*2 f
#define SM_A_HI   8192                // 128x192 bf16 blocked = 49152
#define SM_A_LO   57344
#define SM_B0     106496              // [hi 24576][lo 24576]
#define SM_B1     155648
#define SMEM_SZ   204800

// ---------------- device globals (allocation-free scratch) ----------------
__device__ __align__(128) unsigned char g_Bhi[NTILES * 24576];
__device__ __align__(128) unsigned char g_Blo[NTILES * 24576];
__device__ __align__(128) float g_biasq[512];     // quad-permuted b_ih+b_hh
__device__ __align__(128) float g_h[BB * HH];
__device__ __align__(128) float g_c[BB * HH];

// ---------------- PTX helpers ----------------
__device__ __forceinline__ uint32_t s2u(const void* p) {
    uint32_t a;
    asm("{ .reg .u64 t; cvta.to.shared.u64 t, %1; cvt.u32.u64 %0, t; }" : "=r"(a) : "l"(p));
    return a;
}
__device__ __forceinline__ uint32_t elect1() {
    uint32_t p;
    asm volatile("{ .reg .pred p; elect.sync _|p, 0xFFFFFFFF; selp.b32 %0, 1, 0, p; }" : "=r"(p));
    return p;
}
#define TC_ALLOC(sa, n)   asm volatile("tcgen05.alloc.cta_group::1.sync.aligned.shared::cta.b32 [%0], %1;" :: "r"(sa), "r"((uint32_t)(n)) : "memory")
#define TC_DEALLOC(t, n)  asm volatile("tcgen05.dealloc.cta_group::1.sync.aligned.b32 %0, %1;" :: "r"(t), "r"((uint32_t)(n)))
#define TC_RELINQ()       asm volatile("tcgen05.relinquish_alloc_permit.cta_group::1.sync.aligned;")
#define TC_COMMIT(mb)     asm volatile("tcgen05.commit.cta_group::1.mbarrier::arrive::one.shared::cluster.b64 [%0];" :: "r"(mb) : "memory")
#define TC_WAIT_LD()      asm volatile("tcgen05.wait::ld.sync.aligned;" ::: "memory")
#define TC_FENCE_AFTER()  asm volatile("tcgen05.fence::after_thread_sync;" ::: "memory")
#define TC_FENCE_BEFORE() asm volatile("tcgen05.fence::before_thread_sync;" ::: "memory")
#define FENCE_ASYNC()     asm volatile("fence.proxy.async.shared::cta;" ::: "memory")
#define MBAR_INIT(mb, n)  asm volatile("mbarrier.init.shared.b64 [%0], %1;" :: "r"(mb), "r"((uint32_t)(n)) : "memory")
#define MBAR_INVAL(mb)    asm volatile("mbarrier.inval.shared.b64 [%0];" :: "r"(mb) : "memory")

// Exact example pattern: fast-path try_wait, then suspend-hint loop.
#define MBAR_WAIT(mb, ph) do {                                                     \
    uint32_t _mb = (mb); uint32_t _ph = (uint32_t)(ph); uint32_t _done;            \
    asm volatile("{\n\t.reg .pred p;\n\t"                                          \
        "mbarrier.try_wait.parity.acquire.cta.shared::cta.b64 p, [%1], %2;\n\t"    \
        "selp.b32 %0, 1, 0, p;\n\t}"                                               \
        : "=r"(_done) : "r"(_mb), "r"(_ph) : "memory");                            \
    if (!_done) {                                                                  \
        asm volatile("{\n\t.reg .pred P1;\n\t"                                     \
            "WAIT_LOOP_%=:\n\t"                                                    \
            "mbarrier.try_wait.parity.acquire.cta.shared::cta.b64 P1, [%0], %1, 0x989680;\n\t" \
            "@P1 bra.uni WAIT_DONE_%=;\n\t"                                        \
            "bra.uni WAIT_LOOP_%=;\n\t"                                            \
            "WAIT_DONE_%=:\n\t}"                                                   \
            :: "r"(_mb), "r"(_ph) : "memory");                                     \
    }                                                                              \
} while (0)

__device__ __forceinline__ void mma_ss(uint32_t d, uint64_t a, uint64_t b,
                                       uint32_t idesc, uint32_t en) {
    asm volatile(
        "{\n\t.reg .pred p;\n\t"
        "setp.ne.u32 p, %4, 0;\n\t"
        "tcgen05.mma.cta_group::1.kind::f16 [%0], %1, %2, %3, {%5, %5, %5, %5}, p;\n\t"
        "}"
        :: "r"(d), "l"(a), "l"(b), "r"(idesc), "r"(en), "r"(0u) : "memory");
}
__device__ __forceinline__ void ldtm16(uint32_t* r, uint32_t a) {
    asm volatile(
        "tcgen05.ld.sync.aligned.32x32b.x16.b32 "
        "{%0,%1,%2,%3,%4,%5,%6,%7,%8,%9,%10,%11,%12,%13,%14,%15}, [%16];"
        : "=r"(r[0]), "=r"(r[1]), "=r"(r[2]), "=r"(r[3]),
          "=r"(r[4]), "=r"(r[5]), "=r"(r[6]), "=r"(r[7]),
          "=r"(r[8]), "=r"(r[9]), "=r"(r[10]), "=r"(r[11]),
          "=r"(r[12]), "=r"(r[13]), "=r"(r[14]), "=r"(r[15])
        : "r"(a));
}
__device__ __forceinline__ void cp16(uint32_t saddr, const void* g) {
    asm volatile("cp.async.cg.shared.global [%0], [%1], 16;" :: "r"(saddr), "l"(g));
}
#define CP_COMMIT() asm volatile("cp.async.commit_group;" ::: "memory")
template <int N> __device__ __forceinline__ void cp_wait() {
    asm volatile("cp.async.wait_group %0;" :: "n"(N) : "memory");
}

// SMEM descriptor: SW128, SBO=64, LBO=1, version=1 (Blackwell)
__device__ __forceinline__ uint64_t smem_desc(uint32_t base) {
    const uint64_t D = (uint64_t(2) << 61) | (uint64_t(1) << 46)
                     | (uint64_t(64) << 32) | (uint64_t(1) << 16);
    return D | ((uint64_t)(base >> 4) & 0x3FFF);
}

// blocked SW128 byte offset for bf16 K-major image; natr = #atom-rows (rows/8)
__device__ __forceinline__ uint32_t boff(int row, int kelem, int natr) {
    uint32_t off = ((uint32_t)(row >> 3) + (uint32_t)(kelem >> 6) * natr) * 1024u
                 + (uint32_t)(row & 7) * 128u + (uint32_t)((kelem * 2) & 127);
    return off ^ ((off >> 3) & 0x70);
}

__device__ __forceinline__ uint32_t packbf(float a, float b) {
    __nv_bfloat162 v = __floats2bfloat162_rn(a, b);
    return *reinterpret_cast<uint32_t*>(&v);
}
__device__ __forceinline__ float fsig(float x) {
    x = fminf(fmaxf(x, -30.0f), 30.0f);
    float t = __expf(-x);
    return __fdividef(1.0f, 1.0f + t);
}
__device__ __forceinline__ float ftanh(float x) {
    x = fminf(fmaxf(x, -15.0f), 15.0f);
    float t = __expf(-2.0f * x);
    return __fdividef(1.0f - t, 1.0f + t);
}

// ---------------------------------------------------------------------------
// Prep: bake [W_hh | W_ih] (quad-permuted rows) into swizzled bf16 hi/lo SMEM
// images + permuted fused bias.
// ---------------------------------------------------------------------------
__global__ void prep_kernel(const float* __restrict__ W_ih,
                            const float* __restrict__ b_ih,
                            const float* __restrict__ W_hh,
                            const float* __restrict__ b_hh) {
    int idx = blockIdx.x * blockDim.x + threadIdx.x;
    int stride = gridDim.x * blockDim.x;
    for (int i = idx; i < NTILES * 64 * KK; i += stride) {
        int t = i / (64 * KK);
        int r = i % (64 * KK);
        int n = r / KK, k = r % KK;
        int orow = (n & 3) * HH + t * 16 + (n >> 2);   // gate-quad permutation
        float v = (k < HH) ? W_hh[orow * HH + k] : W_ih[orow * EE + (k - HH)];
        __nv_bfloat16 hi = __float2bfloat16_rn(v);
        __nv_bfloat16 lo = __float2bfloat16_rn(v - __bfloat162float(hi));
        uint32_t o = boff(n, k, 8);
        *(__nv_bfloat16*)(g_Bhi + t * 24576 + o) = hi;
        *(__nv_bfloat16*)(g_Blo + t * 24576 + o) = lo;
    }
    for (int i = idx; i < 512; i += stride) {
        int t = i >> 6, n = i & 63;
        int orow = (n & 3) * HH + t * 16 + (n >> 2);
        g_biasq[i] = b_ih[orow] + b_hh[orow];
    }
}

// ---------------------------------------------------------------------------
// One LSTM step: tcgen05 split-bf16 GEMM + fused cell + readout.
// SERIALIZED per tile: MMA batch -> commit -> wait(all) -> fence -> LDTM
// epilogue. cp.async prefetch of B(t+1) overlaps the MMA.
// ---------------------------------------------------------------------------
__global__ void __launch_bounds__(NTHR, 1)
lstm_step(const float* __restrict__ dA, const float* __restrict__ dB,
          float* __restrict__ outp,
          const float* __restrict__ W_emb, const float* __restrict__ b_emb,
          const float* __restrict__ W_out, const float* __restrict__ b_out,
          int is_first) {
#if HAS_TCGEN05
    extern __shared__ unsigned char smem[];
    const uint32_t sbase = s2u(smem);
    const int tid = threadIdx.x;
    const int wid = tid >> 5, lid = tid & 31;
    const int m0 = blockIdx.x * MT;

    if (wid == 0) { TC_ALLOC(sbase + SM_TMEM, 512); }
    else          { TC_RELINQ(); }
    if (tid == 0) { MBAR_INIT(sbase + SM_MBAR, 1); }

    // prefetch B tile 0 (hi+lo images) into buf0  -> cp.async group 0
    {
        const unsigned char* sh = g_Bhi;
        const unsigned char* sl = g_Blo;
        for (int i = tid; i < 1536; i += NTHR) {
            cp16(sbase + SM_B0 + i * 16, sh + i * 16);
            cp16(sbase + SM_B0 + 24576 + i * 16, sl + i * 16);
        }
        CP_COMMIT();
    }

    // stage biasq + W_out rows 0,1
    for (int i = tid; i < 512; i += NTHR) *(float*)(smem + SM_BIASQ + i * 4) = g_biasq[i];
    for (int i = tid; i < 256; i += NTHR) *(float*)(smem + SM_WOUT + i * 4) = W_out[i];

    // A image: h part (cols 0..127), bf16 hi/lo, blocked swizzled
    for (int g = tid; g < 128 * 16; g += NTHR) {
        int r = g >> 4, c = g & 15;               // c = 8-elem k-chunk
        uint32_t off = ((uint32_t)(r >> 3) + (uint32_t)(c >> 3) * 16) * 1024u
                     + (uint32_t)(r & 7) * 128u + (uint32_t)((c * 16) & 127);
        off ^= (off >> 3) & 0x70;
        uint4 vh, vl;
        if (is_first) {
            vh = make_uint4(0, 0, 0, 0); vl = vh;
        } else {
            const float4* src = (const float4*)(g_h + (size_t)(m0 + r) * HH + c * 8);
            float4 a = src[0], b = src[1];
            float x[8] = {a.x, a.y, a.z, a.w, b.x, b.y, b.z, b.w};
            float hi[8], lo[8];
            #pragma unroll
            for (int q = 0; q < 8; q++) {
                hi[q] = __bfloat162float(__float2bfloat16_rn(x[q]));
                lo[q] = x[q] - hi[q];
            }
            vh = make_uint4(packbf(hi[0], hi[1]), packbf(hi[2], hi[3]),
                            packbf(hi[4], hi[5]), packbf(hi[6], hi[7]));
            vl = make_uint4(packbf(lo[0], lo[1]), packbf(lo[2], lo[3]),
                            packbf(lo[4], lo[5]), packbf(lo[6], lo[7]));
        }
        *(uint4*)(smem + SM_A_HI + off) = vh;
        *(uint4*)(smem + SM_A_LO + off) = vl;
    }
    // A image: e part (cols 128..143) = relu(W_emb @ delta + b_emb)
    if (tid < 128) {
        int r = tid, grow = m0 + r;
        float dx = dA[grow * 2 + 0] - dB[grow * 2 + 0];
        float dy = dA[grow * 2 + 1] - dB[grow * 2 + 1];
        float hi[16], lo[16];
        #pragma unroll
        for (int ei = 0; ei < 16; ei++) {
            float v = fmaf(W_emb[ei * 2 + 0], dx,
                      fmaf(W_emb[ei * 2 + 1], dy, b_emb[ei]));
            v = fmaxf(v, 0.0f);
            hi[ei] = __bfloat162float(__float2bfloat16_rn(v));
            lo[ei] = v - hi[ei];
        }
        uint32_t o0 = boff(r, 128, 16);
        uint32_t o1 = boff(r, 136, 16);
        *(uint4*)(smem + SM_A_HI + o0) = make_uint4(packbf(hi[0], hi[1]), packbf(hi[2], hi[3]),
                                                    packbf(hi[4], hi[5]), packbf(hi[6], hi[7]));
        *(uint4*)(smem + SM_A_HI + o1) = make_uint4(packbf(hi[8], hi[9]), packbf(hi[10], hi[11]),
                                                    packbf(hi[12], hi[13]), packbf(hi[14], hi[15]));
        *(uint4*)(smem + SM_A_LO + o0) = make_uint4(packbf(lo[0], lo[1]), packbf(lo[2], lo[3]),
                                                    packbf(lo[4], lo[5]), packbf(lo[6], lo[7]));
        *(uint4*)(smem + SM_A_LO + o1) = make_uint4(packbf(lo[8], lo[9]), packbf(lo[10], lo[11]),
                                                    packbf(lo[12], lo[13]), packbf(lo[14], lo[15]));
    }
    FENCE_ASYNC();
    __syncthreads();

    uint32_t tmem;
    asm volatile("ld.shared.b32 %0, [%1];" : "=r"(tmem) : "r"(sbase + SM_TMEM));

    const uint64_t adesc_hi = smem_desc(sbase + SM_A_HI);
    const uint64_t adesc_lo = smem_desc(sbase + SM_A_LO);
    const uint32_t IDESC = 0x08100490u;   // f32 acc, bf16 a/b, M=128, N=64

    float s0 = 0.0f, s1 = 0.0f;
    const int mrow = ((wid & 3) << 5) + lid;          // local batch row (TMEM lane)
    const int cbase = (wid >> 2) * 32;                // column half per warp group
    const float* biasq_s = (const float*)(smem + SM_BIASQ);
    const float* wout_s  = (const float*)(smem + SM_WOUT);

    for (int t = 0; t < NTILES; t++) {
        // prefetch B(t+1) into the buffer MMA(t-1) finished with (waited below
        // last iteration) — overlaps with this tile's MMA + epilogue
        if (t + 1 < NTILES) {
            uint32_t dst = sbase + (((t + 1) & 1) ? SM_B1 : SM_B0);
            const unsigned char* sh = g_Bhi + (t + 1) * 24576;
            const unsigned char* sl = g_Blo + (t + 1) * 24576;
            for (int i = tid; i < 1536; i += NTHR) {
                cp16(dst + i * 16, sh + i * 16);
                cp16(dst + 24576 + i * 16, sl + i * 16);
            }
            CP_COMMIT();
            cp_wait<1>();                 // B(t) resident
        } else {
            cp_wait<0>();
        }
        FENCE_ASYNC();
        __syncthreads();

        if (wid == 0) {
            if (elect1()) {
                uint32_t bb = sbase + ((t & 1) ? SM_B1 : SM_B0);
                uint64_t bdesc_hi = smem_desc(bb);
                uint64_t bdesc_lo = smem_desc(bb + 24576);
                uint32_t d = tmem + t * NT;
                int first = 1;
                #pragma unroll
                for (int s = 0; s < 3; s++) {
                    uint64_t ad = (s == 2) ? adesc_lo : adesc_hi;
                    uint64_t bd = (s == 1) ? bdesc_lo : bdesc_hi;
                    #pragma unroll
                    for (int ks = 0; ks < 9; ks++) {
                        uint64_t ka = (uint64_t)((ks >> 2) * 1024 + (ks & 3) * 2);
                        uint64_t kb = (uint64_t)((ks >> 2) * 512 + (ks & 3) * 2);
                        mma_ss(d, ad + ka, bd + kb, IDESC, first ? 0u : 1u);
                        first = 0;
                    }
                }
                TC_COMMIT(sbase + SM_MBAR);
            }
        }

        // ALL threads wait for this tile's MMA completion, then epilogue
        __syncthreads();
        MBAR_WAIT(sbase + SM_MBAR, t & 1);
        TC_FENCE_AFTER();

        #pragma unroll
        for (int cc = 0; cc < 2; cc++) {
            int c = cbase + cc * 16;
            uint32_t r[16];
            ldtm16(r, tmem + t * NT + c);
            TC_WAIT_LD();
            int jb = t * 16 + (c >> 2);
            size_t gidx = (size_t)(m0 + mrow) * HH + jb;
            float4 cold = is_first ? make_float4(0.f, 0.f, 0.f, 0.f)
                                   : *(const float4*)(g_c + gidx);
            float cv[4], hv[4];
            #pragma unroll
            for (int a = 0; a < 4; a++) {
                float bi = biasq_s[t * 64 + c + 4 * a + 0];
                float bf = biasq_s[t * 64 + c + 4 * a + 1];
                float bg = biasq_s[t * 64 + c + 4 * a + 2];
                float bo = biasq_s[t * 64 + c + 4 * a + 3];
                float iv = fsig(__uint_as_float(r[4 * a + 0]) + bi);
                float fv = fsig(__uint_as_float(r[4 * a + 1]) + bf);
                float gv = ftanh(__uint_as_float(r[4 * a + 2]) + bg);
                float ov = fsig(__uint_as_float(r[4 * a + 3]) + bo);
                float co = (a == 0) ? cold.x : (a == 1) ? cold.y : (a == 2) ? cold.z : cold.w;
                float c2 = fmaf(fv, co, iv * gv);
                float h2 = ov * ftanh(c2);
                cv[a] = c2; hv[a] = h2;
                int j = jb + a;
                s0 = fmaf(h2, wout_s[j], s0);
                s1 = fmaf(h2, wout_s[128 + j], s1);
            }
            *(float4*)(g_c + gidx) = make_float4(cv[0], cv[1], cv[2], cv[3]);
            *(float4*)(g_h + gidx) = make_float4(hv[0], hv[1], hv[2], hv[3]);
        }
        TC_FENCE_BEFORE();
        __syncthreads();
    }

    // readout combine: two warp-groups hold complementary j-halves per row
    {
        float* part = (float*)(smem + SM_PART);
        part[(((wid >> 2) * 128) + mrow) * 2 + 0] = s0;
        part[(((wid >> 2) * 128) + mrow) * 2 + 1] = s1;
        __syncthreads();
        if (tid < 128) {
            int m = tid, grow = m0 + m;
            float t0 = part[m * 2 + 0] + part[(128 + m) * 2 + 0] + b_out[0];
            float t1 = part[m * 2 + 1] + part[(128 + m) * 2 + 1] + b_out[1];
            outp[grow * 2 + 0] = dA[grow * 2 + 0] + t0;
            outp[grow * 2 + 1] = dA[grow * 2 + 1] + t1;
        }
    }
    __syncthreads();
    if (tid == 0) { MBAR_INVAL(sbase + SM_MBAR); }
    __syncthreads();
    if (wid == 0) { TC_DEALLOC(tmem, 512); }
#endif  // HAS_TCGEN05
}

// ---------------------------------------------------------------------------
extern "C" void kernel_launch(void* const* d_in, const int* in_sizes, int n_in,
                              void* d_out, int out_size) {
    const float* observed = (const float*)d_in[0];
    const float* W_emb    = (const float*)d_in[1];
    const float* b_emb    = (const float*)d_in[2];
    const float* W_ih     = (const float*)d_in[3];
    const float* b_ih     = (const float*)d_in[4];
    const float* W_hh     = (const float*)d_in[5];
    const float* b_hh     = (const float*)d_in[6];
    const float* W_out    = (const float*)d_in[7];
    const float* b_out    = (const float*)d_in[8];
    float* out = (float*)d_out;

    static bool attr_set = false;
    if (!attr_set) {
        cudaFuncSetAttribute(lstm_step,
                             cudaFuncAttributeMaxDynamicSharedMemorySize, SMEM_SZ);
        attr_set = true;
    }

    prep_kernel<<<288, 256>>>(W_ih, b_ih, W_hh, b_hh);

    const size_t rs = (size_t)BB * 2;
    // observation phase: t = 1..8 -> out rows 0..7
    for (int t = 1; t < NOBS; t++) {
        lstm_step<<<NCTA, NTHR, SMEM_SZ>>>(
            observed + (size_t)t * rs, observed + (size_t)(t - 1) * rs,
            out + (size_t)(t - 1) * rs,
            W_emb, b_emb, W_out, b_out, (t == 1) ? 1 : 0);
    }
    // prediction phase: out rows 8..18
    for (int r = NOBS - 1; r < NOUT; r++) {
        lstm_step<<<NCTA, NTHR, SMEM_SZ>>>(
            out + (size_t)(r - 1) * rs, out + (size_t)(r - 2) * rs,
            out + (size_t)r * rs,
            W_emb, b_emb, W_out, b_out, 0);
    }
}

// round 11
// speedup vs baseline: 2.9489x; 1.0195x over previous
#include <cuda_runtime.h>
#include <cuda_bf16.h>
#include <math.h>
#include <stdint.h>

// Arch guard: the harness's -arch=sm_103a also emits a compute_103 (non-'a')
// PTX pass where tcgen05 is illegal. Real body only in the arch-specific pass.
#if !defined(__CUDA_ARCH__) || defined(__CUDA_ARCH_FEAT_SM103_ALL)
#define HAS_TCGEN05 1
#else
#define HAS_TCGEN05 0
#endif

// ---------------- problem constants ----------------
#define BB   32768
#define HH   128
#define EE   16
#define KK   144          // combined K = H (128) + E (16)
#define NOBS 9
#define NOUT 19

#define MT     128        // M rows per CTA
#define NT     64         // N per ntile
#define NTILES 8          // 8*64 = 512 gate columns
#define NCTA   (BB/MT)    // 256
#define NTHR   256

// ---------------- smem layout (bytes) ----------------
#define SM_TMEM   0
#define SM_MBAR   8
#define SM_BIASQ  16                  // 512 f
#define SM_WOUT   2064                // 256 f (rows 0,1 of W_out)
#define SM_PART   3088                // 2*128*2 f
#define SM_A_HI   8192                // 128x192 bf16 blocked = 49152
#define SM_A_LO   57344
#define SM_B0     106496              // [hi 24576][lo 24576]
#define SM_B1     155648
#define SMEM_SZ   204800

// ---------------- device globals (allocation-free scratch) ----------------
__device__ __align__(128) unsigned char g_Bhi[NTILES * 24576];
__device__ __align__(128) unsigned char g_Blo[NTILES * 24576];
__device__ __align__(128) float g_biasq[512];     // quad-permuted b_ih+b_hh
__device__ __align__(128) float g_h[BB * HH];
__device__ __align__(128) float g_c[BB * HH];

// ---------------- PTX helpers ----------------
__device__ __forceinline__ uint32_t s2u(const void* p) {
    uint32_t a;
    asm("{ .reg .u64 t; cvta.to.shared.u64 t, %1; cvt.u32.u64 %0, t; }" : "=r"(a) : "l"(p));
    return a;
}
__device__ __forceinline__ uint32_t elect1() {
    uint32_t p;
    asm volatile("{ .reg .pred p; elect.sync _|p, 0xFFFFFFFF; selp.b32 %0, 1, 0, p; }" : "=r"(p));
    return p;
}
#define TC_ALLOC(sa, n)   asm volatile("tcgen05.alloc.cta_group::1.sync.aligned.shared::cta.b32 [%0], %1;" :: "r"(sa), "r"((uint32_t)(n)) : "memory")
#define TC_DEALLOC(t, n)  asm volatile("tcgen05.dealloc.cta_group::1.sync.aligned.b32 %0, %1;" :: "r"(t), "r"((uint32_t)(n)))
#define TC_RELINQ()       asm volatile("tcgen05.relinquish_alloc_permit.cta_group::1.sync.aligned;")
#define TC_COMMIT(mb)     asm volatile("tcgen05.commit.cta_group::1.mbarrier::arrive::one.shared::cluster.b64 [%0];" :: "r"(mb) : "memory")
#define TC_WAIT_LD()      asm volatile("tcgen05.wait::ld.sync.aligned;" ::: "memory")
#define TC_FENCE_AFTER()  asm volatile("tcgen05.fence::after_thread_sync;" ::: "memory")
#define TC_FENCE_BEFORE() asm volatile("tcgen05.fence::before_thread_sync;" ::: "memory")
#define FENCE_ASYNC()     asm volatile("fence.proxy.async.shared::cta;" ::: "memory")
#define MBAR_INIT(mb, n)  asm volatile("mbarrier.init.shared.b64 [%0], %1;" :: "r"(mb), "r"((uint32_t)(n)) : "memory")
#define MBAR_INVAL(mb)    asm volatile("mbarrier.inval.shared.b64 [%0];" :: "r"(mb) : "memory")

#define MBAR_WAIT(mb, ph) do {                                                     \
    asm volatile("{\n\t.reg .pred P1;\n\t"                                         \
        "WAIT_LOOP_%=:\n\t"                                                        \
        "mbarrier.try_wait.parity.acquire.cta.shared::cta.b64 P1, [%0], %1, 0x989680;\n\t" \
        "@P1 bra.uni WAIT_DONE_%=;\n\t"                                            \
        "bra.uni WAIT_LOOP_%=;\n\t"                                                \
        "WAIT_DONE_%=:\n\t}"                                                       \
        :: "r"(mb), "r"((uint32_t)(ph)) : "memory");                               \
} while (0)

__device__ __forceinline__ void mma_ss(uint32_t d, uint64_t a, uint64_t b,
                                       uint32_t idesc, uint32_t en) {
    asm volatile(
        "{\n\t.reg .pred p;\n\t"
        "setp.ne.u32 p, %4, 0;\n\t"
        "tcgen05.mma.cta_group::1.kind::f16 [%0], %1, %2, %3, {%5, %5, %5, %5}, p;\n\t"
        "}"
        :: "r"(d), "l"(a), "l"(b), "r"(idesc), "r"(en), "r"(0u) : "memory");
}
__device__ __forceinline__ void ldtm16(uint32_t* r, uint32_t a) {
    asm volatile(
        "tcgen05.ld.sync.aligned.32x32b.x16.b32 "
        "{%0,%1,%2,%3,%4,%5,%6,%7,%8,%9,%10,%11,%12,%13,%14,%15}, [%16];"
        : "=r"(r[0]), "=r"(r[1]), "=r"(r[2]), "=r"(r[3]),
          "=r"(r[4]), "=r"(r[5]), "=r"(r[6]), "=r"(r[7]),
          "=r"(r[8]), "=r"(r[9]), "=r"(r[10]), "=r"(r[11]),
          "=r"(r[12]), "=r"(r[13]), "=r"(r[14]), "=r"(r[15])
        : "r"(a));
}
__device__ __forceinline__ void cp16(uint32_t saddr, const void* g) {
    asm volatile("cp.async.cg.shared.global [%0], [%1], 16;" :: "r"(saddr), "l"(g));
}
#define CP_COMMIT() asm volatile("cp.async.commit_group;" ::: "memory")
template <int N> __device__ __forceinline__ void cp_wait() {
    asm volatile("cp.async.wait_group %0;" :: "n"(N) : "memory");
}

// SMEM descriptor: SW128, SBO=64, LBO=1, version=1 (Blackwell)
__device__ __forceinline__ uint64_t smem_desc(uint32_t base) {
    const uint64_t D = (uint64_t(2) << 61) | (uint64_t(1) << 46)
                     | (uint64_t(64) << 32) | (uint64_t(1) << 16);
    return D | ((uint64_t)(base >> 4) & 0x3FFF);
}

// blocked SW128 byte offset for bf16 K-major image; natr = #atom-rows (rows/8)
__device__ __forceinline__ uint32_t boff(int row, int kelem, int natr) {
    uint32_t off = ((uint32_t)(row >> 3) + (uint32_t)(kelem >> 6) * natr) * 1024u
                 + (uint32_t)(row & 7) * 128u + (uint32_t)((kelem * 2) & 127);
    return off ^ ((off >> 3) & 0x70);
}

__device__ __forceinline__ uint32_t packbf(float a, float b) {
    __nv_bfloat162 v = __floats2bfloat162_rn(a, b);
    return *reinterpret_cast<uint32_t*>(&v);
}
// sigmoid via single-MUFU HW tanh: sigma(x) = 0.5*tanh(x/2) + 0.5
// (pure ALU substitution vs R4; cannot affect launch-ability)
__device__ __forceinline__ float fsig(float x) {
    float y;
    asm("tanh.approx.f32 %0, %1;" : "=f"(y) : "f"(0.5f * x));
    return fmaf(y, 0.5f, 0.5f);
}
__device__ __forceinline__ float ftanh(float x) {
    x = fminf(fmaxf(x, -15.0f), 15.0f);
    float t = __expf(-2.0f * x);
    return __fdividef(1.0f - t, 1.0f + t);
}

// ---------------------------------------------------------------------------
// Prep: bake [W_hh | W_ih] (quad-permuted rows) into swizzled bf16 hi/lo SMEM
// images + permuted fused bias.
// ---------------------------------------------------------------------------
__global__ void prep_kernel(const float* __restrict__ W_ih,
                            const float* __restrict__ b_ih,
                            const float* __restrict__ W_hh,
                            const float* __restrict__ b_hh) {
    int idx = blockIdx.x * blockDim.x + threadIdx.x;
    int stride = gridDim.x * blockDim.x;
    for (int i = idx; i < NTILES * 64 * KK; i += stride) {
        int t = i / (64 * KK);
        int r = i % (64 * KK);
        int n = r / KK, k = r % KK;
        int orow = (n & 3) * HH + t * 16 + (n >> 2);   // gate-quad permutation
        float v = (k < HH) ? W_hh[orow * HH + k] : W_ih[orow * EE + (k - HH)];
        __nv_bfloat16 hi = __float2bfloat16_rn(v);
        __nv_bfloat16 lo = __float2bfloat16_rn(v - __bfloat162float(hi));
        uint32_t o = boff(n, k, 8);
        *(__nv_bfloat16*)(g_Bhi + t * 24576 + o) = hi;
        *(__nv_bfloat16*)(g_Blo + t * 24576 + o) = lo;
    }
    for (int i = idx; i < 512; i += stride) {
        int t = i >> 6, n = i & 63;
        int orow = (n & 3) * HH + t * 16 + (n >> 2);
        g_biasq[i] = b_ih[orow] + b_hh[orow];
    }
}

// ---------------------------------------------------------------------------
// One LSTM step: tcgen05 split-bf16 GEMM + fused cell + readout.
// SERIALIZED per tile (R4-exact): MMA batch -> commit -> sync -> wait(all)
// -> fence -> epilogue. cp.async prefetch of B(t+1) overlaps the MMA.
// ---------------------------------------------------------------------------
__global__ void __launch_bounds__(NTHR, 1)
lstm_step(const float* __restrict__ dA, const float* __restrict__ dB,
          float* __restrict__ outp,
          const float* __restrict__ W_emb, const float* __restrict__ b_emb,
          const float* __restrict__ W_out, const float* __restrict__ b_out,
          int is_first) {
#if HAS_TCGEN05
    extern __shared__ unsigned char smem[];
    const uint32_t sbase = s2u(smem);
    const int tid = threadIdx.x;
    const int wid = tid >> 5, lid = tid & 31;
    const int m0 = blockIdx.x * MT;

    if (wid == 0) { TC_ALLOC(sbase + SM_TMEM, 512); }
    else          { TC_RELINQ(); }
    if (tid == 0) { MBAR_INIT(sbase + SM_MBAR, 1); }

    // prefetch B tile 0 (hi+lo images) into buf0  -> cp.async group 0
    {
        const unsigned char* sh = g_Bhi;
        const unsigned char* sl = g_Blo;
        for (int i = tid; i < 1536; i += NTHR) {
            cp16(sbase + SM_B0 + i * 16, sh + i * 16);
            cp16(sbase + SM_B0 + 24576 + i * 16, sl + i * 16);
        }
        CP_COMMIT();
    }

    // stage biasq + W_out rows 0,1
    for (int i = tid; i < 512; i += NTHR) *(float*)(smem + SM_BIASQ + i * 4) = g_biasq[i];
    for (int i = tid; i < 256; i += NTHR) *(float*)(smem + SM_WOUT + i * 4) = W_out[i];

    // A image: h part (cols 0..127), bf16 hi/lo, blocked swizzled
    for (int g = tid; g < 128 * 16; g += NTHR) {
        int r = g >> 4, c = g & 15;               // c = 8-elem k-chunk
        uint32_t off = ((uint32_t)(r >> 3) + (uint32_t)(c >> 3) * 16) * 1024u
                     + (uint32_t)(r & 7) * 128u + (uint32_t)((c * 16) & 127);
        off ^= (off >> 3) & 0x70;
        uint4 vh, vl;
        if (is_first) {
            vh = make_uint4(0, 0, 0, 0); vl = vh;
        } else {
            const float4* src = (const float4*)(g_h + (size_t)(m0 + r) * HH + c * 8);
            float4 a = src[0], b = src[1];
            float x[8] = {a.x, a.y, a.z, a.w, b.x, b.y, b.z, b.w};
            float hi[8], lo[8];
            #pragma unroll
            for (int q = 0; q < 8; q++) {
                hi[q] = __bfloat162float(__float2bfloat16_rn(x[q]));
                lo[q] = x[q] - hi[q];
            }
            vh = make_uint4(packbf(hi[0], hi[1]), packbf(hi[2], hi[3]),
                            packbf(hi[4], hi[5]), packbf(hi[6], hi[7]));
            vl = make_uint4(packbf(lo[0], lo[1]), packbf(lo[2], lo[3]),
                            packbf(lo[4], lo[5]), packbf(lo[6], lo[7]));
        }
        *(uint4*)(smem + SM_A_HI + off) = vh;
        *(uint4*)(smem + SM_A_LO + off) = vl;
    }
    // A image: e part (cols 128..143) = relu(W_emb @ delta + b_emb)
    if (tid < 128) {
        int r = tid, grow = m0 + r;
        float dx = dA[grow * 2 + 0] - dB[grow * 2 + 0];
        float dy = dA[grow * 2 + 1] - dB[grow * 2 + 1];
        float hi[16], lo[16];
        #pragma unroll
        for (int ei = 0; ei < 16; ei++) {
            float v = fmaf(W_emb[ei * 2 + 0], dx,
                      fmaf(W_emb[ei * 2 + 1], dy, b_emb[ei]));
            v = fmaxf(v, 0.0f);
            hi[ei] = __bfloat162float(__float2bfloat16_rn(v));
            lo[ei] = v - hi[ei];
        }
        uint32_t o0 = boff(r, 128, 16);
        uint32_t o1 = boff(r, 136, 16);
        *(uint4*)(smem + SM_A_HI + o0) = make_uint4(packbf(hi[0], hi[1]), packbf(hi[2], hi[3]),
                                                    packbf(hi[4], hi[5]), packbf(hi[6], hi[7]));
        *(uint4*)(smem + SM_A_HI + o1) = make_uint4(packbf(hi[8], hi[9]), packbf(hi[10], hi[11]),
                                                    packbf(hi[12], hi[13]), packbf(hi[14], hi[15]));
        *(uint4*)(smem + SM_A_LO + o0) = make_uint4(packbf(lo[0], lo[1]), packbf(lo[2], lo[3]),
                                                    packbf(lo[4], lo[5]), packbf(lo[6], lo[7]));
        *(uint4*)(smem + SM_A_LO + o1) = make_uint4(packbf(lo[8], lo[9]), packbf(lo[10], lo[11]),
                                                    packbf(lo[12], lo[13]), packbf(lo[14], lo[15]));
    }
    FENCE_ASYNC();
    __syncthreads();

    uint32_t tmem;
    asm volatile("ld.shared.b32 %0, [%1];" : "=r"(tmem) : "r"(sbase + SM_TMEM));

    const uint64_t adesc_hi = smem_desc(sbase + SM_A_HI);
    const uint64_t adesc_lo = smem_desc(sbase + SM_A_LO);
    const uint32_t IDESC = 0x08100490u;   // f32 acc, bf16 a/b, M=128, N=64

    float s0 = 0.0f, s1 = 0.0f;
    const int mrow = ((wid & 3) << 5) + lid;          // local batch row (TMEM lane)
    const int cbase = (wid >> 2) * 32;                // column half per warp group
    const float* biasq_s = (const float*)(smem + SM_BIASQ);
    const float* wout_s  = (const float*)(smem + SM_WOUT);

    for (int t = 0; t < NTILES; t++) {
        // prefetch B(t+1) into the buffer MMA(t-1) finished with (waited below
        // last iteration) — overlaps with this tile's MMA + epilogue
        if (t + 1 < NTILES) {
            uint32_t dst = sbase + (((t + 1) & 1) ? SM_B1 : SM_B0);
            const unsigned char* sh = g_Bhi + (t + 1) * 24576;
            const unsigned char* sl = g_Blo + (t + 1) * 24576;
            for (int i = tid; i < 1536; i += NTHR) {
                cp16(dst + i * 16, sh + i * 16);
                cp16(dst + 24576 + i * 16, sl + i * 16);
            }
            CP_COMMIT();
            cp_wait<1>();                 // B(t) resident
        } else {
            cp_wait<0>();
        }
        FENCE_ASYNC();
        __syncthreads();

        if (wid == 0) {
            if (elect1()) {
                uint32_t bb = sbase + ((t & 1) ? SM_B1 : SM_B0);
                uint64_t bdesc_hi = smem_desc(bb);
                uint64_t bdesc_lo = smem_desc(bb + 24576);
                uint32_t d = tmem + t * NT;
                int first = 1;
                #pragma unroll
                for (int s = 0; s < 3; s++) {
                    uint64_t ad = (s == 2) ? adesc_lo : adesc_hi;
                    uint64_t bd = (s == 1) ? bdesc_lo : bdesc_hi;
                    #pragma unroll
                    for (int ks = 0; ks < 9; ks++) {
                        uint64_t ka = (uint64_t)((ks >> 2) * 1024 + (ks & 3) * 2);
                        uint64_t kb = (uint64_t)((ks >> 2) * 512 + (ks & 3) * 2);
                        mma_ss(d, ad + ka, bd + kb, IDESC, first ? 0u : 1u);
                        first = 0;
                    }
                }
                TC_COMMIT(sbase + SM_MBAR);
            }
        }

        // ALL threads wait for this tile's MMA completion, then epilogue
        __syncthreads();
        MBAR_WAIT(sbase + SM_MBAR, t & 1);
        TC_FENCE_AFTER();

        #pragma unroll
        for (int cc = 0; cc < 2; cc++) {
            int c = cbase + cc * 16;
            uint32_t r[16];
            ldtm16(r, tmem + t * NT + c);
            TC_WAIT_LD();
            int jb = t * 16 + (c >> 2);
            size_t gidx = (size_t)(m0 + mrow) * HH + jb;
            float4 cold = is_first ? make_float4(0.f, 0.f, 0.f, 0.f)
                                   : *(const float4*)(g_c + gidx);
            float cv[4], hv[4];
            #pragma unroll
            for (int a = 0; a < 4; a++) {
                float bi = biasq_s[t * 64 + c + 4 * a + 0];
                float bf = biasq_s[t * 64 + c + 4 * a + 1];
                float bg = biasq_s[t * 64 + c + 4 * a + 2];
                float bo = biasq_s[t * 64 + c + 4 * a + 3];
                float iv = fsig(__uint_as_float(r[4 * a + 0]) + bi);
                float fv = fsig(__uint_as_float(r[4 * a + 1]) + bf);
                float gv = ftanh(__uint_as_float(r[4 * a + 2]) + bg);
                float ov = fsig(__uint_as_float(r[4 * a + 3]) + bo);
                float co = (a == 0) ? cold.x : (a == 1) ? cold.y : (a == 2) ? cold.z : cold.w;
                float c2 = fmaf(fv, co, iv * gv);
                float h2 = ov * ftanh(c2);
                cv[a] = c2; hv[a] = h2;
                int j = jb + a;
                s0 = fmaf(h2, wout_s[j], s0);
                s1 = fmaf(h2, wout_s[128 + j], s1);
            }
            *(float4*)(g_c + gidx) = make_float4(cv[0], cv[1], cv[2], cv[3]);
            *(float4*)(g_h + gidx) = make_float4(hv[0], hv[1], hv[2], hv[3]);
        }
        TC_FENCE_BEFORE();
        __syncthreads();
    }

    // readout combine: two warp-groups hold complementary j-halves per row
    {
        float* part = (float*)(smem + SM_PART);
        part[(((wid >> 2) * 128) + mrow) * 2 + 0] = s0;
        part[(((wid >> 2) * 128) + mrow) * 2 + 1] = s1;
        __syncthreads();
        if (tid < 128) {
            int m = tid, grow = m0 + m;
            float t0 = part[m * 2 + 0] + part[(128 + m) * 2 + 0] + b_out[0];
            float t1 = part[m * 2 + 1] + part[(128 + m) * 2 + 1] + b_out[1];
            outp[grow * 2 + 0] = dA[grow * 2 + 0] + t0;
            outp[grow * 2 + 1] = dA[grow * 2 + 1] + t1;
        }
    }
    __syncthreads();
    if (tid == 0) { MBAR_INVAL(sbase + SM_MBAR); }
    __syncthreads();
    if (wid == 0) { TC_DEALLOC(tmem, 512); }
#endif  // HAS_TCGEN05
}

// ---------------------------------------------------------------------------
extern "C" void kernel_launch(void* const* d_in, const int* in_sizes, int n_in,
                              void* d_out, int out_size) {
    const float* observed = (const float*)d_in[0];
    const float* W_emb    = (const float*)d_in[1];
    const float* b_emb    = (const float*)d_in[2];
    const float* W_ih     = (const float*)d_in[3];
    const float* b_ih     = (const float*)d_in[4];
    const float* W_hh     = (const float*)d_in[5];
    const float* b_hh     = (const float*)d_in[6];
    const float* W_out    = (const float*)d_in[7];
    const float* b_out    = (const float*)d_in[8];
    float* out = (float*)d_out;

    static bool attr_set = false;
    if (!attr_set) {
        cudaFuncSetAttribute(lstm_step,
                             cudaFuncAttributeMaxDynamicSharedMemorySize, SMEM_SZ);
        attr_set = true;
    }

    prep_kernel<<<288, 256>>>(W_ih, b_ih, W_hh, b_hh);

    const size_t rs = (size_t)BB * 2;
    // observation phase: t = 1..8 -> out rows 0..7
    for (int t = 1; t < NOBS; t++) {
        lstm_step<<<NCTA, NTHR, SMEM_SZ>>>(
            observed + (size_t)t * rs, observed + (size_t)(t - 1) * rs,
            out + (size_t)(t - 1) * rs,
            W_emb, b_emb, W_out, b_out, (t == 1) ? 1 : 0);
    }
    // prediction phase: out rows 8..18
    for (int r = NOBS - 1; r < NOUT; r++) {
        lstm_step<<<NCTA, NTHR, SMEM_SZ>>>(
            out + (size_t)(r - 1) * rs, out + (size_t)(r - 2) * rs,
            out + (size_t)r * rs,
            W_emb, b_emb, W_out, b_out, 0);
    }
}